// round 1
// baseline (speedup 1.0000x reference)
#include <cuda_runtime.h>
#include <cuda_bf16.h>
#include <cstdint>

// ---------------- device scratch (static allocation only) ----------------
__device__ float d_pw[4096 * 16];        // softmax pattern weights * intensity
__device__ float d_meanpart[4 * 8 * 128];
__device__ int   d_k;

__device__ __forceinline__ float gelu_erf(float v) {
    return 0.5f * v * (1.0f + erff(v * 0.70710678118654752440f));
}
__device__ __forceinline__ float sigmoidf(float v) {
    return 1.0f / (1.0f + expf(-v));
}

// ---------------- Kernel A: per-token selector + intensity ----------------
// grid 512, block 256 (8 warps = 8 tokens per CTA). dynamic smem 109568 B.
__global__ void __launch_bounds__(256) kA(
    const float* __restrict__ x, const float* __restrict__ ctx,
    const float* __restrict__ w1, const float* __restrict__ b1,   // [256,32],[32]
    const float* __restrict__ w2, const float* __restrict__ b2,   // [32,16],[16]
    const float* __restrict__ wi1, const float* __restrict__ bi1, // [256,64],[64]
    const float* __restrict__ wi2, const float* __restrict__ bi2) // [64,1],[1]
{
    extern __shared__ float sm[];
    float* ws1  = sm;            // 8192
    float* ws2  = sm + 8192;     // 512
    float* wi1s = sm + 8704;     // 16384
    float* cs   = sm + 25088;    // 8*256
    float* h1s  = sm + 27136;    // 8*32

    int tid = threadIdx.x;
    for (int i = tid; i < 2048; i += 256) ((float4*)ws1)[i]  = ((const float4*)w1)[i];
    for (int i = tid; i < 128;  i += 256) ((float4*)ws2)[i]  = ((const float4*)w2)[i];
    for (int i = tid; i < 4096; i += 256) ((float4*)wi1s)[i] = ((const float4*)wi1)[i];

    int w = tid >> 5, lane = tid & 31;
    int t = blockIdx.x * 8 + w;

    // combined = [x(128), ctx(128)] into smem
    float4 xv = ((const float4*)x)[t * 32 + lane];
    float4 cv = ((const float4*)ctx)[t * 32 + lane];
    ((float4*)(cs + w * 256))[lane]       = xv;
    ((float4*)(cs + w * 256 + 128))[lane] = cv;
    __syncthreads();

    const float* c = cs + w * 256;

    // h1[lane] = gelu(b1 + c . W1[:,lane])
    float acc = b1[lane];
    #pragma unroll 8
    for (int i = 0; i < 256; i++) acc = fmaf(c[i], ws1[i * 32 + lane], acc);
    h1s[w * 32 + lane] = gelu_erf(acc);
    __syncwarp();

    // logits (lanes 0..15) + softmax over 16
    float l = (lane < 16) ? b2[lane] : __int_as_float(0xff800000);
    if (lane < 16) {
        #pragma unroll
        for (int i = 0; i < 32; i++) l = fmaf(h1s[w * 32 + i], ws2[i * 16 + lane], l);
    }
    float m = l;
    #pragma unroll
    for (int off = 8; off >= 1; off >>= 1)
        m = fmaxf(m, __shfl_xor_sync(0xffffffffu, m, off));
    float e = (lane < 16) ? expf(l - m) : 0.0f;
    float s = e;
    #pragma unroll
    for (int off = 8; off >= 1; off >>= 1)
        s += __shfl_xor_sync(0xffffffffu, s, off);
    float pw = e / s;

    // intensity = sigmoid(gelu(c@Wi1+bi1) @ wi2 + bi2)
    float a0 = bi1[lane], a1 = bi1[lane + 32];
    #pragma unroll 8
    for (int i = 0; i < 256; i++) {
        float ci = c[i];
        a0 = fmaf(ci, wi1s[i * 64 + lane], a0);
        a1 = fmaf(ci, wi1s[i * 64 + lane + 32], a1);
    }
    float part = gelu_erf(a0) * wi2[lane] + gelu_erf(a1) * wi2[lane + 32];
    #pragma unroll
    for (int off = 16; off >= 1; off >>= 1)
        part += __shfl_xor_sync(0xffffffffu, part, off);
    float inten = sigmoidf(part + bi2[0]);

    if (lane < 16) d_pw[t * 16 + lane] = pw * inten;
}

// ---------------- Kernel B1: partial batch means of x ----------------
// grid 32 (b*8+chunk), block 128
__global__ void kB1(const float* __restrict__ x) {
    int b = blockIdx.x >> 3, chunk = blockIdx.x & 7;
    int d = threadIdx.x;
    const float* p = x + (size_t)(b * 1024 + chunk * 128) * 128 + d;
    float s = 0.0f;
    for (int i = 0; i < 128; i++) s += p[i * 128];
    d_meanpart[blockIdx.x * 128 + d] = s;
}

// ---------------- Kernel B2: window MLP -> global k ----------------
// grid 1, block 128
__global__ void kB2(const float* __restrict__ ww1, const float* __restrict__ bw1,
                    const float* __restrict__ ww2, const float* __restrict__ bw2)
{
    __shared__ float mb[128];
    __shared__ float hsm[64];
    int tid = threadIdx.x;
    float winsum = 0.0f;
    for (int b = 0; b < 4; b++) {
        float mv = 0.0f;
        for (int cix = 0; cix < 8; cix++) mv += d_meanpart[(b * 8 + cix) * 128 + tid];
        mb[tid] = mv * (1.0f / 1024.0f);
        __syncthreads();
        if (tid < 64) {
            float a = bw1[tid];
            for (int dd = 0; dd < 128; dd++) a = fmaf(mb[dd], ww1[dd * 64 + tid], a);
            hsm[tid] = gelu_erf(a);
        }
        __syncthreads();
        if (tid == 0) {
            float s2 = bw2[0];
            for (int j = 0; j < 64; j++) s2 = fmaf(hsm[j], ww2[j], s2);
            float wv = sigmoidf(s2);
            winsum += wv * 3840.0f + 256.0f;  // window size
        }
        __syncthreads();
    }
    if (tid == 0) {
        float spars = 0.1f * ((winsum * 0.25f) * (1.0f / 4096.0f)); // exact pow2 scalings
        int k = (int)floorf(16384.0f * spars);
        if (k < 1) k = 1;
        d_k = k;
    }
}

// ---------------- Kernel C: flow GEMM -> d_out (scaled by intensity) ----------------
// grid 256 (16 tokens each), block 256
__global__ void __launch_bounds__(256) kC(const float* __restrict__ pat,
                                          float* __restrict__ out)
{
    __shared__ unsigned long long pwp[256];  // 16 tokens x 16 patterns, packed (v,v)
    int tid = threadIdx.x;
    int tile = blockIdx.x;
    {
        unsigned int b = __float_as_uint(d_pw[tile * 256 + tid]);
        pwp[tid] = ((unsigned long long)b << 32) | (unsigned long long)b;
    }
    __syncthreads();

    const ulonglong2* p2 = (const ulonglong2*)pat;
    ulonglong2* o2 = (ulonglong2*)out;

    for (int it = 0; it < 16; ++it) {
        int d = it * 1024 + tid * 4;
        unsigned long long pa[16], pb[16];
        #pragma unroll
        for (int p = 0; p < 16; p++) {
            ulonglong2 v = p2[(p * 16384 + d) >> 2];
            pa[p] = v.x; pb[p] = v.y;
        }
        for (int t = 0; t < 16; t++) {
            unsigned long long a0 = 0ULL, a1 = 0ULL;
            const unsigned long long* pwt = &pwp[t * 16];
            #pragma unroll
            for (int p = 0; p < 16; p++) {
                unsigned long long wv = pwt[p];
                asm("fma.rn.f32x2 %0, %1, %2, %3;" : "=l"(a0) : "l"(pa[p]), "l"(wv), "l"(a0));
                asm("fma.rn.f32x2 %0, %1, %2, %3;" : "=l"(a1) : "l"(pb[p]), "l"(wv), "l"(a1));
            }
            ulonglong2 r; r.x = a0; r.y = a1;
            o2[((size_t)(tile * 16 + t) * 16384 + d) >> 2] = r;
        }
    }
}

// ---------------- Kernel D: exact per-token top-k mask (in place) ----------------
// grid 4096, block 256. dynamic smem = 16384*4 + 2048*4 = 73728 B.
__global__ void __launch_bounds__(256) kD(float* __restrict__ out)
{
    extern __shared__ float sm[];
    float* row = sm;                                  // 16384 floats
    unsigned int* hist = (unsigned int*)(sm + 16384); // 2048 bins
    __shared__ unsigned int csum[256];
    __shared__ unsigned int s_sel, s_rem, s_pfx;

    int tid = threadIdx.x;
    int token = blockIdx.x;
    float4* row4 = (float4*)row;
    float4* g4 = (float4*)(out + (size_t)token * 16384);

    #pragma unroll
    for (int i = 0; i < 16; i++) row4[tid + i * 256] = g4[tid + i * 256];
    if (tid == 0) { s_rem = (unsigned int)d_k; s_pfx = 0u; }
    __syncthreads();

    #pragma unroll 1
    for (int pass = 0; pass < 3; pass++) {
        for (int i = tid; i < 2048; i += 256) hist[i] = 0u;
        __syncthreads();
        unsigned int pfx = s_pfx;
        for (int i = 0; i < 16; i++) {
            float4 v = row4[tid + i * 256];
            float vals[4] = {v.x, v.y, v.z, v.w};
            #pragma unroll
            for (int j = 0; j < 4; j++) {
                unsigned int key = __float_as_uint(fabsf(vals[j]));
                bool cond; unsigned int bin;
                if (pass == 0)      { cond = true;                    bin = key >> 21; }
                else if (pass == 1) { cond = ((key >> 21) == pfx);    bin = (key >> 10) & 2047u; }
                else                { cond = ((key >> 10) == pfx);    bin = key & 1023u; }
                if (cond) {
                    unsigned int peers = __match_any_sync(__activemask(), bin);
                    unsigned int lane = threadIdx.x & 31;
                    if ((__ffs(peers) - 1) == (int)lane)
                        atomicAdd(&hist[bin], __popc(peers));
                }
            }
        }
        __syncthreads();

        // find bin containing the s_rem-th largest (scan from top)
        unsigned int cs = 0;
        #pragma unroll
        for (int j = 0; j < 8; j++) cs += hist[tid * 8 + j];
        csum[tid] = cs;
        __syncthreads();
        if (tid < 32) {
            unsigned int ws = 0;
            #pragma unroll
            for (int j = 0; j < 8; j++) ws += csum[tid * 8 + j];
            unsigned int sfx = ws;
            #pragma unroll
            for (int off = 1; off <= 16; off <<= 1) {
                unsigned int t2 = __shfl_down_sync(0xffffffffu, sfx, off);
                if (tid + off < 32) sfx += t2;
            }
            unsigned int rem_t = s_rem;
            unsigned int bal = __ballot_sync(0xffffffffu, sfx >= rem_t);
            int J = 31 - __clz((int)bal);
            if (tid == J) {
                unsigned int rem = rem_t - (sfx - ws);
                int chunk = J * 8;
                for (int cix = J * 8 + 7; cix >= J * 8; --cix) {
                    unsigned int cc = csum[cix];
                    if (rem <= cc) { chunk = cix; break; }
                    rem -= cc;
                }
                int bin = chunk * 8;
                for (int bix = chunk * 8 + 7; bix >= chunk * 8; --bix) {
                    unsigned int hc = hist[bix];
                    if (rem <= hc) { bin = bix; break; }
                    rem -= hc;
                }
                s_sel = (unsigned int)bin;
                s_rem = rem;
            }
        }
        __syncthreads();
        if (tid == 0) {
            if (pass == 0)      s_pfx = s_sel;
            else if (pass == 1) s_pfx = (s_pfx << 11) | s_sel;
            else                s_pfx = (s_pfx << 10) | s_sel;  // final threshold key
        }
        __syncthreads();
    }

    unsigned int thrkey = s_pfx;
    #pragma unroll
    for (int i = 0; i < 16; i++) {
        float4 v = row4[tid + i * 256];
        v.x = (__float_as_uint(fabsf(v.x)) >= thrkey) ? v.x : 0.0f;
        v.y = (__float_as_uint(fabsf(v.y)) >= thrkey) ? v.y : 0.0f;
        v.z = (__float_as_uint(fabsf(v.z)) >= thrkey) ? v.z : 0.0f;
        v.w = (__float_as_uint(fabsf(v.w)) >= thrkey) ? v.w : 0.0f;
        g4[tid + i * 256] = v;
    }
}

// ---------------- launch ----------------
extern "C" void kernel_launch(void* const* d_in, const int* in_sizes, int n_in,
                              void* d_out, int out_size)
{
    const float* x    = (const float*)d_in[0];
    const float* ctx  = (const float*)d_in[1];
    const float* pat  = (const float*)d_in[2];
    const float* w1   = (const float*)d_in[3];
    const float* b1   = (const float*)d_in[4];
    const float* w2   = (const float*)d_in[5];
    const float* b2   = (const float*)d_in[6];
    const float* wi1  = (const float*)d_in[7];
    const float* bi1  = (const float*)d_in[8];
    const float* wi2  = (const float*)d_in[9];
    const float* bi2  = (const float*)d_in[10];
    const float* ww1  = (const float*)d_in[11];
    const float* bw1  = (const float*)d_in[12];
    const float* ww2  = (const float*)d_in[13];
    const float* bw2  = (const float*)d_in[14];
    float* out = (float*)d_out;

    cudaFuncSetAttribute(kA, cudaFuncAttributeMaxDynamicSharedMemorySize, 109568);
    cudaFuncSetAttribute(kD, cudaFuncAttributeMaxDynamicSharedMemorySize, 73728);

    kA<<<512, 256, 109568>>>(x, ctx, w1, b1, w2, b2, wi1, bi1, wi2, bi2);
    kB1<<<32, 128>>>(x);
    kB2<<<1, 128>>>(ww1, bw1, ww2, bw2);
    kC<<<256, 256>>>(pat, out);
    kD<<<4096, 256, 73728>>>(out);
}